// round 12
// baseline (speedup 1.0000x reference)
#include <cuda_runtime.h>
#include <math.h>
#include <stdint.h>

// Problem dims (fixed by the dataset)
#define NR 4096           // bs*seq
#define KC 8192           // codebook size
#define DD 512            // feature dim
#define BSZ 8
#define TOT (NR * KC)

// ---------------- scratch (static __device__, allocation-free) ----------------
__device__ float g_logits[(size_t)NR * KC];   // 134 MB
__device__ float g_zz[NR];
__device__ float g_cc[KC];
__device__ float g_colsum[KC];
__device__ float g_scal[2];  // [0] = sum(p*logp), [1] = sum(diff^2)

// ---------------- zero accumulators (graph replays!) ----------------
__global__ void k_zero() {
    int i = blockIdx.x * blockDim.x + threadIdx.x;
    if (i < KC) g_colsum[i] = 0.f;
    if (i < 2)  g_scal[i]   = 0.f;
}

// ---------------- row squared norms ----------------
__global__ void k_sumsq(const float* __restrict__ Z, const float* __restrict__ CB) {
    int warp = (blockIdx.x * blockDim.x + threadIdx.x) >> 5;
    int lane = threadIdx.x & 31;
    if (warp >= NR + KC) return;
    const float* p = (warp < NR) ? (Z + (size_t)warp * DD)
                                 : (CB + (size_t)(warp - NR) * DD);
    float s = 0.f;
    #pragma unroll 4
    for (int i = lane; i < DD; i += 32) { float v = p[i]; s += v * v; }
    #pragma unroll
    for (int o = 16; o; o >>= 1) s += __shfl_xor_sync(0xffffffffu, s, o);
    if (lane == 0) { if (warp < NR) g_zz[warp] = s; else g_cc[warp - NR] = s; }
}

// ---------------- Threefry-2x32 gumbel (partitionable), pure fn of index ------
__device__ __forceinline__ float gumbel_of(unsigned i) {
    unsigned x0 = 0u, x1 = i;
    const unsigned k0 = 0u, k1 = 42u, k2 = 0x1BD11BDAu ^ k0 ^ k1;
    x0 += k0; x1 += k1;
#define TFR(r) { x0 += x1; x1 = __funnelshift_l(x1, x1, r); x1 ^= x0; }
    TFR(13) TFR(15) TFR(26) TFR(6)   x0 += k1; x1 += k2 + 1u;
    TFR(17) TFR(29) TFR(16) TFR(24)  x0 += k2; x1 += k0 + 2u;
    TFR(13) TFR(15) TFR(26) TFR(6)   x0 += k0; x1 += k1 + 3u;
    TFR(17) TFR(29) TFR(16) TFR(24)  x0 += k1; x1 += k2 + 4u;
    TFR(13) TFR(15) TFR(26) TFR(6)   x0 += k2; x1 += k0 + 5u;
#undef TFR
    unsigned bits = x0 ^ x1;
    float u = __uint_as_float(0x3f800000u | (bits >> 9)) - 1.0f;
    float x = u - 1.0f;                       // exact (Sterbenz) for u in [0.5,1]
    float pl = 1.f + x * (-0.5f + x * (0.33333334f + x * (-0.25f +
               x * (0.2f + x * (-0.16666667f + x * 0.14285715f)))));
    float ts = -x * pl;                       // accurate -ln(u), u near 1
    float tm = -__logf(u + 1e-10f);
    float t = (u > 0.9f) ? ts : tm;
    return -__logf(t + 1e-10f);
}

// ---------------- GEMM1: logits[n,k] = w*(2*Z.C^T - zz - cc) ----------------
// 128x128x16 tile, 256 threads, z-order warps, double-buffered smem,
// packed fma.rn.f32x2: 4 row-pairs x 8 cols per thread.
// A smem: [2][16][136] plain.  B smem: [2][16][320] value-DUPLICATED (v,v)
//   with dup-addr D(j) = (j/16)*40 + (j%16)*2  (8-float pad per 32 -> banks
//   of the 4 colT groups are {0,16,8,24}: conflict-free LDS.128).
#define BM1 128
#define BN1 128
#define BK1 16
#define LDT 136
#define LDB2 320
#define A_FL (2 * BK1 * LDT)     // 4352 floats
#define B_FL (2 * BK1 * LDB2)    // 10240 floats
#define SMEM_G1 ((A_FL + B_FL) * 4)   // 58368 bytes

__device__ __forceinline__ uint32_t smem_u32(const void* p) {
    uint32_t a;
    asm("{ .reg .u64 t; cvta.to.shared.u64 t, %1; cvt.u32.u64 %0, t; }"
        : "=r"(a) : "l"(p));
    return a;
}
#define FMA2(c, a, b) \
    asm volatile("fma.rn.f32x2 %0, %1, %2, %0;" : "+l"(c) : "l"(a), "l"(b))
#define LDS_V2U64(r0, r1, addr) \
    asm volatile("ld.shared.v2.u64 {%0,%1}, [%2];" : "=l"(r0), "=l"(r1) : "r"(addr))
#define UNPK(lo, hi, c) \
    asm volatile("mov.b64 {%0,%1}, %2;" : "=f"(lo), "=f"(hi) : "l"(c))

__global__ __launch_bounds__(256) void k_gemm_logits(
    const float* __restrict__ Z, const float* __restrict__ CB,
    const float* __restrict__ varq) {
    extern __shared__ float dynsm[];
    float* a_sh = dynsm;             // [2][16][LDT]
    float* b_sh = dynsm + A_FL;      // [2][16][LDB2] duplicated
    const int tid = threadIdx.x;
    const int lane = tid & 31, warp = tid >> 5;
    const int rowT = lane >> 2, colT = lane & 3;        // 8x4 lanes
    const int warpRow = warp & 1, warpCol = warp >> 1;  // 2x4 warps
    const int aOff = warpRow * 64 + rowT * 8;
    const int bOff = warpCol * 32 + colT * 8;
    const int dOff = (bOff >> 4) * 40 + (bOff & 15) * 2;   // dup addr of bOff
    const int rowBase = blockIdx.y * BM1, colBase = blockIdx.x * BN1;
    const int lr = tid >> 2;     // 0..63 loader row
    const int lc = tid & 3;      // 0..3

    const float* Ap = Z  + (size_t)(rowBase + lr) * DD + lc * 4;
    const float* Bp = CB + (size_t)(colBase + lr) * DD + lc * 4;
    const int d0 = (lr >> 4) * 40 + (lr & 15) * 2;          // D(lr)
    const int d1 = ((lr + 64) >> 4) * 40 + (lr & 15) * 2;   // D(lr+64)

    float4 va0 = *(const float4*)(Ap);
    float4 va1 = *(const float4*)(Ap + 64 * DD);
    float4 vb0 = *(const float4*)(Bp);
    float4 vb1 = *(const float4*)(Bp + 64 * DD);

#define STORE_TILE(buf) do {                                                   \
    float* ap = a_sh + (buf) * (BK1 * LDT);                                    \
    float* bp = b_sh + (buf) * (BK1 * LDB2);                                   \
    ap[(lc*4+0)*LDT + lr]      = va0.x; ap[(lc*4+1)*LDT + lr]      = va0.y;    \
    ap[(lc*4+2)*LDT + lr]      = va0.z; ap[(lc*4+3)*LDT + lr]      = va0.w;    \
    ap[(lc*4+0)*LDT + lr + 64] = va1.x; ap[(lc*4+1)*LDT + lr + 64] = va1.y;    \
    ap[(lc*4+2)*LDT + lr + 64] = va1.z; ap[(lc*4+3)*LDT + lr + 64] = va1.w;    \
    *(float2*)&bp[(lc*4+0)*LDB2 + d0] = make_float2(vb0.x, vb0.x);             \
    *(float2*)&bp[(lc*4+1)*LDB2 + d0] = make_float2(vb0.y, vb0.y);             \
    *(float2*)&bp[(lc*4+2)*LDB2 + d0] = make_float2(vb0.z, vb0.z);             \
    *(float2*)&bp[(lc*4+3)*LDB2 + d0] = make_float2(vb0.w, vb0.w);             \
    *(float2*)&bp[(lc*4+0)*LDB2 + d1] = make_float2(vb1.x, vb1.x);             \
    *(float2*)&bp[(lc*4+1)*LDB2 + d1] = make_float2(vb1.y, vb1.y);             \
    *(float2*)&bp[(lc*4+2)*LDB2 + d1] = make_float2(vb1.z, vb1.z);             \
    *(float2*)&bp[(lc*4+3)*LDB2 + d1] = make_float2(vb1.w, vb1.w);             \
} while (0)

    STORE_TILE(0);
    __syncthreads();

    uint64_t acc[4][8];
    #pragma unroll
    for (int r = 0; r < 4; r++)
        #pragma unroll
        for (int j = 0; j < 8; j++) acc[r][j] = 0ull;

    const uint32_t sA = smem_u32(a_sh) + aOff * 4;
    const uint32_t sB = smem_u32(b_sh) + dOff * 4;

    const int NIT = DD / BK1;   // 32
    for (int kk = 0; kk < NIT; kk++) {
        const int cur = kk & 1, nxt = cur ^ 1;
        if (kk + 1 < NIT) {
            const float* Ap2 = Ap + (kk + 1) * BK1;
            const float* Bp2 = Bp + (kk + 1) * BK1;
            va0 = *(const float4*)(Ap2);
            va1 = *(const float4*)(Ap2 + 64 * DD);
            vb0 = *(const float4*)(Bp2);
            vb1 = *(const float4*)(Bp2 + 64 * DD);
        }
        {
            const uint32_t aBuf = sA + cur * (BK1 * LDT * 4);
            const uint32_t bBuf = sB + cur * (BK1 * LDB2 * 4);
            #pragma unroll
            for (int p = 0; p < BK1; p++) {
                const uint32_t aA = aBuf + p * (LDT * 4);
                const uint32_t bA = bBuf + p * (LDB2 * 4);
                uint64_t a01, a23, a45, a67, q0, q1, q2, q3;
                LDS_V2U64(a01, a23, aA);
                LDS_V2U64(a45, a67, aA + 16);
                LDS_V2U64(q0, q1, bA);
                LDS_V2U64(q2, q3, bA + 16);
                FMA2(acc[0][0], a01, q0); FMA2(acc[1][0], a23, q0);
                FMA2(acc[2][0], a45, q0); FMA2(acc[3][0], a67, q0);
                FMA2(acc[0][1], a01, q1); FMA2(acc[1][1], a23, q1);
                FMA2(acc[2][1], a45, q1); FMA2(acc[3][1], a67, q1);
                FMA2(acc[0][2], a01, q2); FMA2(acc[1][2], a23, q2);
                FMA2(acc[2][2], a45, q2); FMA2(acc[3][2], a67, q2);
                FMA2(acc[0][3], a01, q3); FMA2(acc[1][3], a23, q3);
                FMA2(acc[2][3], a45, q3); FMA2(acc[3][3], a67, q3);
                LDS_V2U64(q0, q1, bA + 32);
                LDS_V2U64(q2, q3, bA + 48);
                FMA2(acc[0][4], a01, q0); FMA2(acc[1][4], a23, q0);
                FMA2(acc[2][4], a45, q0); FMA2(acc[3][4], a67, q0);
                FMA2(acc[0][5], a01, q1); FMA2(acc[1][5], a23, q1);
                FMA2(acc[2][5], a45, q1); FMA2(acc[3][5], a67, q1);
                FMA2(acc[0][6], a01, q2); FMA2(acc[1][6], a23, q2);
                FMA2(acc[2][6], a45, q2); FMA2(acc[3][6], a67, q2);
                FMA2(acc[0][7], a01, q3); FMA2(acc[1][7], a23, q3);
                FMA2(acc[2][7], a45, q3); FMA2(acc[3][7], a67, q3);
            }
        }
        if (kk + 1 < NIT) STORE_TILE(nxt);
        __syncthreads();
    }

    const float w = 0.5f / fmaxf(varq[0], 1e-10f);
    float cc[8];
    #pragma unroll
    for (int q = 0; q < 8; q++) cc[q] = g_cc[colBase + bOff + q];
    #pragma unroll
    for (int r = 0; r < 4; r++) {
        float lo[8], hi[8];
        #pragma unroll
        for (int j = 0; j < 8; j++) UNPK(lo[j], hi[j], acc[r][j]);
        #pragma unroll
        for (int h = 0; h < 2; h++) {
            const float* v = h ? hi : lo;
            int n = rowBase + aOff + 2 * r + h;
            float zzn = g_zz[n];
            float* dst = g_logits + (size_t)n * KC + colBase + bOff;
            float4 v0, v1;
            v0.x = w * (2.f * v[0] - zzn - cc[0]);
            v0.y = w * (2.f * v[1] - zzn - cc[1]);
            v0.z = w * (2.f * v[2] - zzn - cc[2]);
            v0.w = w * (2.f * v[3] - zzn - cc[3]);
            v1.x = w * (2.f * v[4] - zzn - cc[4]);
            v1.y = w * (2.f * v[5] - zzn - cc[5]);
            v1.z = w * (2.f * v[6] - zzn - cc[6]);
            v1.w = w * (2.f * v[7] - zzn - cc[7]);
            *(float4*)(dst)     = v0;
            *(float4*)(dst + 4) = v1;
        }
    }
#undef STORE_TILE
}

// ---------------- mega kernel: stats + colsum + sparse gumbel decode + diff ----
#define CCAP 256
__global__ __launch_bounds__(256) void k_mega(const float* __restrict__ Z,
                                              const float* __restrict__ CB,
                                              float* __restrict__ out) {
    const int n = blockIdx.x;
    const float* __restrict__ lrow = g_logits + (size_t)n * KC;
    const unsigned ibase = (unsigned)n * KC;
    const int t = threadIdx.x;

    float m1 = -1e30f, Z1 = 0.f, T1 = 0.f;
    for (int k = t * 4; k < KC; k += 1024) {
        float4 l4 = *(const float4*)(lrow + k);
        #pragma unroll
        for (int q = 0; q < 4; q++) {
            float l = (q == 0) ? l4.x : (q == 1) ? l4.y : (q == 2) ? l4.z : l4.w;
            if (l > m1) {
                float d = m1 - l;
                float sc = __expf(d);
                T1 = sc * (T1 + d * Z1);
                Z1 *= sc;
                m1 = l;
            }
            float e = __expf(l - m1);
            Z1 += e; T1 += e * (l - m1);
        }
    }
    __shared__ float sm[256], sz[256], st[256];
    __shared__ float s_fin[6];
    __shared__ int ccnt;
    __shared__ int   cidx[CCAP];
    __shared__ float cy[CCAP];
    sm[t] = m1; sz[t] = Z1; st[t] = T1;
    __syncthreads();
    for (int s = 128; s; s >>= 1) {
        if (t < s) {
            int o = t + s;
            float M = fmaxf(sm[t], sm[o]);
            float da = sm[t] - M, db = sm[o] - M;
            float ea = __expf(da), eb = __expf(db);
            st[t] = ea * (st[t] + da * sz[t]) + eb * (st[o] + db * sz[o]);
            sz[t] = ea * sz[t] + eb * sz[o];
            sm[t] = M;
        }
        __syncthreads();
    }
    if (t == 0) {
        float M = sm[0], Zz = sz[0], T = st[0];
        atomicAdd(&g_scal[0], T / Zz - logf(Zz));   // exact row sum p*logp
        s_fin[0] = M;
        s_fin[1] = 1.f / Zz;
        s_fin[2] = M + logf(Zz) - 20.723f;          // p > 1e-9 cut
        s_fin[3] = M - 28.5f;                       // candidate cut
        ccnt = 0;
    }
    __syncthreads();
    const float m1v = s_fin[0], iZ1 = s_fin[1], lpc = s_fin[2], ccut = s_fin[3];

    for (int k = t * 4; k < KC; k += 1024) {
        float4 l4 = *(const float4*)(lrow + k);
        #pragma unroll
        for (int q = 0; q < 4; q++) {
            float l = (q == 0) ? l4.x : (q == 1) ? l4.y : (q == 2) ? l4.z : l4.w;
            if (l > lpc)
                atomicAdd(&g_colsum[k + q], __expf(l - m1v) * iZ1);
            if (l > ccut) {
                int s = atomicAdd(&ccnt, 1);
                if (s < CCAP) {
                    cidx[s] = k + q;
                    cy[s]   = 2.0f * (l + gumbel_of(ibase + k + q));
                }
            }
        }
    }
    __syncthreads();
    const int cnt = min(ccnt, CCAP);

    // m2 = max over candidates
    float lm = -1e30f;
    for (int j = t; j < cnt; j += 256) lm = fmaxf(lm, cy[j]);
    sm[t] = lm;
    __syncthreads();
    for (int s = 128; s; s >>= 1) {
        if (t < s) sm[t] = fmaxf(sm[t], sm[t + s]);
        __syncthreads();
    }
    if (t == 0) s_fin[4] = sm[0];
    __syncthreads();
    const float m2v = s_fin[4];

    // Z2 over candidates
    float lz = 0.f;
    for (int j = t; j < cnt; j += 256) lz += __expf(cy[j] - m2v);
    sm[t] = lz;
    __syncthreads();
    for (int s = 128; s; s >>= 1) {
        if (t < s) sm[t] += sm[t + s];
        __syncthreads();
    }
    if (t == 0) s_fin[5] = 1.f / sm[0];
    __syncthreads();
    const float iZ2 = s_fin[5];
    for (int j = t; j < cnt; j += 256) cy[j] = __expf(cy[j] - m2v) * iZ2;
    __syncthreads();

    // decode: z_dec[n][:] = sum_j E_j * CB[cidx_j][:]; fused diff^2
    const int c0 = t * 2;
    float a0 = 0.f, a1 = 0.f;
    for (int j = 0; j < cnt; j++) {
        float e = cy[j];
        float2 cb = *(const float2*)(CB + (size_t)cidx[j] * DD + c0);
        a0 += e * cb.x;
        a1 += e * cb.y;
    }
    out[(size_t)n * DD + c0]     = a0;
    out[(size_t)n * DD + c0 + 1] = a1;
    float2 z2 = *(const float2*)(Z + (size_t)n * DD + c0);
    float d0 = z2.x - a0, d1 = z2.y - a1;
    sm[t] = d0 * d0 + d1 * d1;
    __syncthreads();
    for (int s = 128; s; s >>= 1) {
        if (t < s) sm[t] += sm[t + s];
        __syncthreads();
    }
    if (t == 0) atomicAdd(&g_scal[1], sm[0]);
}

// ---------------- finalize loss + perplexity ----------------
__global__ __launch_bounds__(256) void k_final(const float* __restrict__ varq,
                                               float* __restrict__ out, int out_size) {
    __shared__ float sh[256];
    float s = 0.f;
    for (int k = threadIdx.x; k < KC; k += 256) {
        float a = g_colsum[k] * (1.0f / (float)NR);
        s += a * logf(a + 1e-7f);
    }
    sh[threadIdx.x] = s;
    __syncthreads();
    for (int t = 128; t; t >>= 1) {
        if (threadIdx.x < t) sh[threadIdx.x] += sh[threadIdx.x + t];
        __syncthreads();
    }
    if (threadIdx.x == 0) {
        float w = 0.5f / fmaxf(varq[0], 1e-10f);
        float loss = g_scal[0] / (float)BSZ + w * g_scal[1] / (float)BSZ;
        float perp = expf(-sh[0]);
        if (out_size >= NR * DD + 2) {
            out[(size_t)NR * DD]     = loss;
            out[(size_t)NR * DD + 1] = perp;
        }
    }
}

// ---------------- launch ----------------
extern "C" void kernel_launch(void* const* d_in, const int* in_sizes, int n_in,
                              void* d_out, int out_size) {
    const float *Z = 0, *varq = 0, *CB = 0;
    for (int i = 0; i < n_in; i++) {
        if (in_sizes[i] == 1)            varq = (const float*)d_in[i];
        else if (in_sizes[i] == NR * DD) Z    = (const float*)d_in[i];
        else if (in_sizes[i] == KC * DD) CB   = (const float*)d_in[i];
    }
    float* out = (float*)d_out;

    cudaFuncSetAttribute(k_gemm_logits,
                         cudaFuncAttributeMaxDynamicSharedMemorySize, SMEM_G1);

    k_zero<<<(KC + 255) / 256, 256>>>();
    k_sumsq<<<((NR + KC) * 32 + 255) / 256, 256>>>(Z, CB);
    k_gemm_logits<<<dim3(KC / BN1, NR / BM1), 256, SMEM_G1>>>(Z, CB, varq);
    k_mega<<<NR, 256>>>(Z, CB, out);
    k_final<<<1, 256>>>(varq, out, out_size);
}

// round 13
// speedup vs baseline: 1.2629x; 1.2629x over previous
#include <cuda_runtime.h>
#include <math.h>
#include <stdint.h>

// Problem dims (fixed by the dataset)
#define NR 4096           // bs*seq
#define KC 8192           // codebook size
#define DD 512            // feature dim
#define BSZ 8
#define TOT (NR * KC)

// ---------------- scratch (static __device__, allocation-free) ----------------
__device__ float g_logits[(size_t)NR * KC];   // 134 MB
__device__ float g_cc[KC];
__device__ float g_colsum[KC];
__device__ float g_scal[2];  // [0] = sum(p*logp), [1] = sum(diff^2)

// ---------------- zero accumulators (graph replays!) ----------------
__global__ void k_zero() {
    int i = blockIdx.x * blockDim.x + threadIdx.x;
    if (i < KC) g_colsum[i] = 0.f;
    if (i < 2)  g_scal[i]   = 0.f;
}

// ---------------- codebook squared norms (zz dropped: row-shift invariant) ----
__global__ void k_sumsq(const float* __restrict__ CB) {
    int warp = (blockIdx.x * blockDim.x + threadIdx.x) >> 5;
    int lane = threadIdx.x & 31;
    if (warp >= KC) return;
    const float* p = CB + (size_t)warp * DD;
    float s = 0.f;
    #pragma unroll 4
    for (int i = lane; i < DD; i += 32) { float v = p[i]; s += v * v; }
    #pragma unroll
    for (int o = 16; o; o >>= 1) s += __shfl_xor_sync(0xffffffffu, s, o);
    if (lane == 0) g_cc[warp] = s;
}

// ---------------- Threefry-2x32 gumbel (partitionable), pure fn of index ------
__device__ __forceinline__ float gumbel_of(unsigned i) {
    unsigned x0 = 0u, x1 = i;
    const unsigned k0 = 0u, k1 = 42u, k2 = 0x1BD11BDAu ^ k0 ^ k1;
    x0 += k0; x1 += k1;
#define TFR(r) { x0 += x1; x1 = __funnelshift_l(x1, x1, r); x1 ^= x0; }
    TFR(13) TFR(15) TFR(26) TFR(6)   x0 += k1; x1 += k2 + 1u;
    TFR(17) TFR(29) TFR(16) TFR(24)  x0 += k2; x1 += k0 + 2u;
    TFR(13) TFR(15) TFR(26) TFR(6)   x0 += k0; x1 += k1 + 3u;
    TFR(17) TFR(29) TFR(16) TFR(24)  x0 += k1; x1 += k2 + 4u;
    TFR(13) TFR(15) TFR(26) TFR(6)   x0 += k2; x1 += k0 + 5u;
#undef TFR
    unsigned bits = x0 ^ x1;
    float u = __uint_as_float(0x3f800000u | (bits >> 9)) - 1.0f;
    float x = u - 1.0f;                       // exact (Sterbenz) for u in [0.5,1]
    float pl = 1.f + x * (-0.5f + x * (0.33333334f + x * (-0.25f +
               x * (0.2f + x * (-0.16666667f + x * 0.14285715f)))));
    float ts = -x * pl;                       // accurate -ln(u), u near 1
    float tm = -__logf(u + 1e-10f);
    float t = (u > 0.9f) ? ts : tm;
    return -__logf(t + 1e-10f);
}

// ---------------- GEMM1: logits[n,k] = w*(2*Z.C^T - cc)  (zz shift dropped) ---
// 128x128x16 tile, 256 threads, 8x8 micro-tile, z-order warps, double-buffered.
// LDT=132: loader STS stride*4 mod 32 = 16 -> 2-way (minimum possible with
// 16B-aligned rows), vs 4-way at 136. All LDS patterns stay conflict-free.
#define BM1 128
#define BN1 128
#define BK1 16
#define LDT 132
__global__ __launch_bounds__(256) void k_gemm_logits(
    const float* __restrict__ Z, const float* __restrict__ CB,
    const float* __restrict__ varq) {
    __shared__ float As[2][BK1][LDT];
    __shared__ float Bs[2][BK1][LDT];
    const int tid = threadIdx.x;
    const int lane = tid & 31, warp = tid >> 5;
    const int rowT = lane >> 2, colT = lane & 3;   // 8x4 lanes in warp
    const int warpRow = warp & 1, warpCol = warp >> 1;  // 2x4 warps
    const int aOff = warpRow * 64 + rowT * 8;      // row offset of 8-row strip
    const int bOff = warpCol * 32 + colT * 8;      // col offset of 8-col strip
    const int rowBase = blockIdx.y * BM1, colBase = blockIdx.x * BN1;
    const int lr = tid >> 2;     // 0..63 loader row
    const int lc = tid & 3;      // 0..3

    const float* Ap = Z  + (size_t)(rowBase + lr) * DD + lc * 4;
    const float* Bp = CB + (size_t)(colBase + lr) * DD + lc * 4;

    float4 va0 = *(const float4*)(Ap);
    float4 va1 = *(const float4*)(Ap + 64 * DD);
    float4 vb0 = *(const float4*)(Bp);
    float4 vb1 = *(const float4*)(Bp + 64 * DD);

    As[0][lc*4+0][lr]    = va0.x; As[0][lc*4+1][lr]    = va0.y;
    As[0][lc*4+2][lr]    = va0.z; As[0][lc*4+3][lr]    = va0.w;
    As[0][lc*4+0][lr+64] = va1.x; As[0][lc*4+1][lr+64] = va1.y;
    As[0][lc*4+2][lr+64] = va1.z; As[0][lc*4+3][lr+64] = va1.w;
    Bs[0][lc*4+0][lr]    = vb0.x; Bs[0][lc*4+1][lr]    = vb0.y;
    Bs[0][lc*4+2][lr]    = vb0.z; Bs[0][lc*4+3][lr]    = vb0.w;
    Bs[0][lc*4+0][lr+64] = vb1.x; Bs[0][lc*4+1][lr+64] = vb1.y;
    Bs[0][lc*4+2][lr+64] = vb1.z; Bs[0][lc*4+3][lr+64] = vb1.w;
    __syncthreads();

    float acc[8][8];
    #pragma unroll
    for (int i = 0; i < 8; i++)
        #pragma unroll
        for (int j = 0; j < 8; j++) acc[i][j] = 0.f;

    const int NIT = DD / BK1;   // 32
    for (int kk = 0; kk < NIT; kk++) {
        const int cur = kk & 1, nxt = cur ^ 1;
        if (kk + 1 < NIT) {
            const float* Ap2 = Ap + (kk + 1) * BK1;
            const float* Bp2 = Bp + (kk + 1) * BK1;
            va0 = *(const float4*)(Ap2);
            va1 = *(const float4*)(Ap2 + 64 * DD);
            vb0 = *(const float4*)(Bp2);
            vb1 = *(const float4*)(Bp2 + 64 * DD);
        }
        #pragma unroll
        for (int p = 0; p < BK1; p++) {
            float a[8], b[8];
            *(float4*)(a)     = *(const float4*)&As[cur][p][aOff];
            *(float4*)(a + 4) = *(const float4*)&As[cur][p][aOff + 4];
            *(float4*)(b)     = *(const float4*)&Bs[cur][p][bOff];
            *(float4*)(b + 4) = *(const float4*)&Bs[cur][p][bOff + 4];
            #pragma unroll
            for (int i = 0; i < 8; i++)
                #pragma unroll
                for (int j = 0; j < 8; j++) acc[i][j] += a[i] * b[j];
        }
        if (kk + 1 < NIT) {
            As[nxt][lc*4+0][lr]    = va0.x; As[nxt][lc*4+1][lr]    = va0.y;
            As[nxt][lc*4+2][lr]    = va0.z; As[nxt][lc*4+3][lr]    = va0.w;
            As[nxt][lc*4+0][lr+64] = va1.x; As[nxt][lc*4+1][lr+64] = va1.y;
            As[nxt][lc*4+2][lr+64] = va1.z; As[nxt][lc*4+3][lr+64] = va1.w;
            Bs[nxt][lc*4+0][lr]    = vb0.x; Bs[nxt][lc*4+1][lr]    = vb0.y;
            Bs[nxt][lc*4+2][lr]    = vb0.z; Bs[nxt][lc*4+3][lr]    = vb0.w;
            Bs[nxt][lc*4+0][lr+64] = vb1.x; Bs[nxt][lc*4+1][lr+64] = vb1.y;
            Bs[nxt][lc*4+2][lr+64] = vb1.z; Bs[nxt][lc*4+3][lr+64] = vb1.w;
        }
        __syncthreads();
    }

    const float w = 0.5f / fmaxf(varq[0], 1e-10f);
    float cc[8];
    #pragma unroll
    for (int q = 0; q < 8; q++) cc[q] = g_cc[colBase + bOff + q];
    #pragma unroll
    for (int i = 0; i < 8; i++) {
        int n = rowBase + aOff + i;
        float* dst = g_logits + (size_t)n * KC + colBase + bOff;
        float4 v0, v1;
        v0.x = w * (2.f * acc[i][0] - cc[0]);
        v0.y = w * (2.f * acc[i][1] - cc[1]);
        v0.z = w * (2.f * acc[i][2] - cc[2]);
        v0.w = w * (2.f * acc[i][3] - cc[3]);
        v1.x = w * (2.f * acc[i][4] - cc[4]);
        v1.y = w * (2.f * acc[i][5] - cc[5]);
        v1.z = w * (2.f * acc[i][6] - cc[6]);
        v1.w = w * (2.f * acc[i][7] - cc[7]);
        *(float4*)(dst)     = v0;
        *(float4*)(dst + 4) = v1;
    }
}

// ---------------- mega kernel: stats + colsum + sparse gumbel decode + diff ----
// Phase 1: branch-free online (m1,Z1,T1) over logits (exact kld_discrete).
// Phase 2: colsum atomics for p>1e-9; Threefry ONLY for l > m1-28.5.
// Phase 3: m2/Z2 over candidates; z_dec = sum E_k*CB[k]; fused diff^2.
#define CCAP 256
__global__ __launch_bounds__(256) void k_mega(const float* __restrict__ Z,
                                              const float* __restrict__ CB,
                                              float* __restrict__ out) {
    const int n = blockIdx.x;
    const float* __restrict__ lrow = g_logits + (size_t)n * KC;
    const unsigned ibase = (unsigned)n * KC;
    const int t = threadIdx.x;

    float m1 = -3.0e30f, Z1 = 0.f, T1 = 0.f;
    for (int k = t * 4; k < KC; k += 1024) {
        float4 l4 = *(const float4*)(lrow + k);
        #pragma unroll
        for (int q = 0; q < 4; q++) {
            float l = (q == 0) ? l4.x : (q == 1) ? l4.y : (q == 2) ? l4.z : l4.w;
            float mn = fmaxf(m1, l);
            float d  = fmaxf(m1 - mn, -100.f);   // finite: kills -inf*0 at init
            float sc = __expf(d);
            float e  = __expf(l - mn);
            T1 = sc * (T1 + d * Z1) + e * (l - mn);
            Z1 = sc * Z1 + e;
            m1 = mn;
        }
    }
    __shared__ float sm[256], sz[256], st[256];
    __shared__ float s_fin[6];
    __shared__ int ccnt;
    __shared__ int   cidx[CCAP];
    __shared__ float cy[CCAP];
    sm[t] = m1; sz[t] = Z1; st[t] = T1;
    __syncthreads();
    for (int s = 128; s; s >>= 1) {
        if (t < s) {
            int o = t + s;
            float M = fmaxf(sm[t], sm[o]);
            float da = sm[t] - M, db = sm[o] - M;
            float ea = __expf(da), eb = __expf(db);
            st[t] = ea * (st[t] + da * sz[t]) + eb * (st[o] + db * sz[o]);
            sz[t] = ea * sz[t] + eb * sz[o];
            sm[t] = M;
        }
        __syncthreads();
    }
    if (t == 0) {
        float M = sm[0], Zz = sz[0], T = st[0];
        atomicAdd(&g_scal[0], T / Zz - logf(Zz));   // exact row sum p*logp
        s_fin[0] = M;
        s_fin[1] = 1.f / Zz;
        s_fin[2] = M + logf(Zz) - 20.723f;          // p > 1e-9 cut
        s_fin[3] = M - 28.5f;                       // candidate cut
        ccnt = 0;
    }
    __syncthreads();
    const float m1v = s_fin[0], iZ1 = s_fin[1], lpc = s_fin[2], ccut = s_fin[3];

    for (int k = t * 4; k < KC; k += 1024) {
        float4 l4 = *(const float4*)(lrow + k);
        #pragma unroll
        for (int q = 0; q < 4; q++) {
            float l = (q == 0) ? l4.x : (q == 1) ? l4.y : (q == 2) ? l4.z : l4.w;
            if (l > lpc)
                atomicAdd(&g_colsum[k + q], __expf(l - m1v) * iZ1);
            if (l > ccut) {
                int s = atomicAdd(&ccnt, 1);
                if (s < CCAP) {
                    cidx[s] = k + q;
                    cy[s]   = 2.0f * (l + gumbel_of(ibase + k + q));
                }
            }
        }
    }
    __syncthreads();
    const int cnt = min(ccnt, CCAP);

    // m2 = max over candidates
    float lm = -1e30f;
    for (int j = t; j < cnt; j += 256) lm = fmaxf(lm, cy[j]);
    sm[t] = lm;
    __syncthreads();
    for (int s = 128; s; s >>= 1) {
        if (t < s) sm[t] = fmaxf(sm[t], sm[t + s]);
        __syncthreads();
    }
    if (t == 0) s_fin[4] = sm[0];
    __syncthreads();
    const float m2v = s_fin[4];

    // Z2 over candidates
    float lz = 0.f;
    for (int j = t; j < cnt; j += 256) lz += __expf(cy[j] - m2v);
    sm[t] = lz;
    __syncthreads();
    for (int s = 128; s; s >>= 1) {
        if (t < s) sm[t] += sm[t + s];
        __syncthreads();
    }
    if (t == 0) s_fin[5] = 1.f / sm[0];
    __syncthreads();
    const float iZ2 = s_fin[5];
    for (int j = t; j < cnt; j += 256) cy[j] = __expf(cy[j] - m2v) * iZ2;
    __syncthreads();

    // decode: z_dec[n][:] = sum_j E_j * CB[cidx_j][:]; fused diff^2
    const int c0 = t * 2;
    float a0 = 0.f, a1 = 0.f;
    for (int j = 0; j < cnt; j++) {
        float e = cy[j];
        float2 cb = *(const float2*)(CB + (size_t)cidx[j] * DD + c0);
        a0 += e * cb.x;
        a1 += e * cb.y;
    }
    out[(size_t)n * DD + c0]     = a0;
    out[(size_t)n * DD + c0 + 1] = a1;
    float2 z2 = *(const float2*)(Z + (size_t)n * DD + c0);
    float d0 = z2.x - a0, d1 = z2.y - a1;
    sm[t] = d0 * d0 + d1 * d1;
    __syncthreads();
    for (int s = 128; s; s >>= 1) {
        if (t < s) sm[t] += sm[t + s];
        __syncthreads();
    }
    if (t == 0) atomicAdd(&g_scal[1], sm[0]);
}

// ---------------- finalize loss + perplexity ----------------
__global__ __launch_bounds__(256) void k_final(const float* __restrict__ varq,
                                               float* __restrict__ out, int out_size) {
    __shared__ float sh[256];
    float s = 0.f;
    for (int k = threadIdx.x; k < KC; k += 256) {
        float a = g_colsum[k] * (1.0f / (float)NR);
        s += a * logf(a + 1e-7f);
    }
    sh[threadIdx.x] = s;
    __syncthreads();
    for (int t = 128; t; t >>= 1) {
        if (threadIdx.x < t) sh[threadIdx.x] += sh[threadIdx.x + t];
        __syncthreads();
    }
    if (threadIdx.x == 0) {
        float w = 0.5f / fmaxf(varq[0], 1e-10f);
        float loss = g_scal[0] / (float)BSZ + w * g_scal[1] / (float)BSZ;
        float perp = expf(-sh[0]);
        if (out_size >= NR * DD + 2) {
            out[(size_t)NR * DD]     = loss;
            out[(size_t)NR * DD + 1] = perp;
        }
    }
}

// ---------------- launch ----------------
extern "C" void kernel_launch(void* const* d_in, const int* in_sizes, int n_in,
                              void* d_out, int out_size) {
    const float *Z = 0, *varq = 0, *CB = 0;
    for (int i = 0; i < n_in; i++) {
        if (in_sizes[i] == 1)            varq = (const float*)d_in[i];
        else if (in_sizes[i] == NR * DD) Z    = (const float*)d_in[i];
        else if (in_sizes[i] == KC * DD) CB   = (const float*)d_in[i];
    }
    float* out = (float*)d_out;

    k_zero<<<(KC + 255) / 256, 256>>>();
    k_sumsq<<<(KC * 32 + 255) / 256, 256>>>(CB);
    k_gemm_logits<<<dim3(KC / BN1, NR / BM1), 256>>>(Z, CB, varq);
    k_mega<<<NR, 256>>>(Z, CB, out);
    k_final<<<1, 256>>>(varq, out, out_size);
}

// round 14
// speedup vs baseline: 1.6315x; 1.2919x over previous
#include <cuda_runtime.h>
#include <math.h>
#include <stdint.h>

// Problem dims (fixed by the dataset)
#define NR 4096           // bs*seq
#define KC 8192           // codebook size
#define DD 512            // feature dim
#define BSZ 8
#define TOT (NR * KC)

// ---------------- scratch (static __device__, allocation-free) ----------------
__device__ float g_logits[(size_t)NR * KC];   // 134 MB
__device__ float g_cc[KC];
__device__ float g_colsum[KC];
__device__ float g_scal[2];  // [0] = sum(p*logp), [1] = sum(diff^2)

// ---------------- zero accumulators (graph replays!) ----------------
__global__ void k_zero() {
    int i = blockIdx.x * blockDim.x + threadIdx.x;
    if (i < KC) g_colsum[i] = 0.f;
    if (i < 2)  g_scal[i]   = 0.f;
}

// ---------------- codebook squared norms ----------------
__global__ void k_sumsq(const float* __restrict__ CB) {
    int warp = (blockIdx.x * blockDim.x + threadIdx.x) >> 5;
    int lane = threadIdx.x & 31;
    if (warp >= KC) return;
    const float* p = CB + (size_t)warp * DD;
    float s = 0.f;
    #pragma unroll 4
    for (int i = lane; i < DD; i += 32) { float v = p[i]; s += v * v; }
    #pragma unroll
    for (int o = 16; o; o >>= 1) s += __shfl_xor_sync(0xffffffffu, s, o);
    if (lane == 0) g_cc[warp] = s;
}

// ---------------- Threefry-2x32 gumbel (partitionable), pure fn of index ------
__device__ __forceinline__ float gumbel_of(unsigned i) {
    unsigned x0 = 0u, x1 = i;
    const unsigned k0 = 0u, k1 = 42u, k2 = 0x1BD11BDAu ^ k0 ^ k1;
    x0 += k0; x1 += k1;
#define TFR(r) { x0 += x1; x1 = __funnelshift_l(x1, x1, r); x1 ^= x0; }
    TFR(13) TFR(15) TFR(26) TFR(6)   x0 += k1; x1 += k2 + 1u;
    TFR(17) TFR(29) TFR(16) TFR(24)  x0 += k2; x1 += k0 + 2u;
    TFR(13) TFR(15) TFR(26) TFR(6)   x0 += k0; x1 += k1 + 3u;
    TFR(17) TFR(29) TFR(16) TFR(24)  x0 += k1; x1 += k2 + 4u;
    TFR(13) TFR(15) TFR(26) TFR(6)   x0 += k2; x1 += k0 + 5u;
#undef TFR
    unsigned bits = x0 ^ x1;
    float u = __uint_as_float(0x3f800000u | (bits >> 9)) - 1.0f;
    float x = u - 1.0f;                       // exact (Sterbenz) for u in [0.5,1]
    float pl = 1.f + x * (-0.5f + x * (0.33333334f + x * (-0.25f +
               x * (0.2f + x * (-0.16666667f + x * 0.14285715f)))));
    float ts = -x * pl;                       // accurate -ln(u), u near 1
    float tm = -__logf(u + 1e-10f);
    float t = (u > 0.9f) ? ts : tm;
    return -__logf(t + 1e-10f);
}

// ---------------- GEMM1 via mma.sync tf32 (3-way split) ----------------------
// logits[n,k] = w*(2*Z.C^T - cc). 128x128x16 CTA tile, 256 threads.
// Warps z-order 2x4; warp tile 64x32 = 4x4 m16n8k8 fragments.
// smem untransposed [row][k] with pitch 20: fragment LDS conflict-free
// ((gr*20+ct) mod 32 covers all banks), loader uses STS.128.
#define BK1 16
#define KP 20
#define MMA3(d, A, B) asm volatile( \
    "mma.sync.aligned.m16n8k8.row.col.f32.tf32.tf32.f32 " \
    "{%0,%1,%2,%3}, {%4,%5,%6,%7}, {%8,%9}, {%0,%1,%2,%3};" \
    : "+f"((d)[0]), "+f"((d)[1]), "+f"((d)[2]), "+f"((d)[3]) \
    : "r"((A)[0]), "r"((A)[1]), "r"((A)[2]), "r"((A)[3]), \
      "r"((B)[0]), "r"((B)[1]))

__global__ __launch_bounds__(256, 2) void k_gemm_logits(
    const float* __restrict__ Z, const float* __restrict__ CB,
    const float* __restrict__ varq) {
    __shared__ __align__(16) float As[2][128][KP];
    __shared__ __align__(16) float Bs[2][128][KP];
    const int tid = threadIdx.x;
    const int lane = tid & 31, warp = tid >> 5;
    const int gr = lane >> 2, ct = lane & 3;
    const int warpRow = warp & 1, warpCol = warp >> 1;
    const int aBase = warpRow * 64;        // warp row offset (64 rows)
    const int bBase = warpCol * 32;        // warp col offset (32 cols)
    const int rowBase = blockIdx.y * 128, colBase = blockIdx.x * 128;
    const int lr = tid >> 2;     // 0..63 loader row
    const int lc = tid & 3;      // 0..3  loader k-slot

    const float* Ap = Z  + (size_t)(rowBase + lr) * DD + lc * 4;
    const float* Bp = CB + (size_t)(colBase + lr) * DD + lc * 4;

    float4 va0 = *(const float4*)(Ap);
    float4 va1 = *(const float4*)(Ap + 64 * DD);
    float4 vb0 = *(const float4*)(Bp);
    float4 vb1 = *(const float4*)(Bp + 64 * DD);

#define STORE_TILE(buf) do {                             \
    *(float4*)&As[buf][lr][lc * 4]      = va0;           \
    *(float4*)&As[buf][lr + 64][lc * 4] = va1;           \
    *(float4*)&Bs[buf][lr][lc * 4]      = vb0;           \
    *(float4*)&Bs[buf][lr + 64][lc * 4] = vb1;           \
} while (0)

    STORE_TILE(0);
    __syncthreads();

    float acc[4][4][4];
    #pragma unroll
    for (int mi = 0; mi < 4; mi++)
        #pragma unroll
        for (int nj = 0; nj < 4; nj++)
            #pragma unroll
            for (int r = 0; r < 4; r++) acc[mi][nj][r] = 0.f;

    const int NIT = DD / BK1;   // 32
    for (int kk = 0; kk < NIT; kk++) {
        const int cur = kk & 1, nxt = cur ^ 1;
        if (kk + 1 < NIT) {
            const float* Ap2 = Ap + (kk + 1) * BK1;
            const float* Bp2 = Bp + (kk + 1) * BK1;
            va0 = *(const float4*)(Ap2);
            va1 = *(const float4*)(Ap2 + 64 * DD);
            vb0 = *(const float4*)(Bp2);
            vb1 = *(const float4*)(Bp2 + 64 * DD);
        }
        #pragma unroll
        for (int ks = 0; ks < 2; ks++) {
            // A fragments (4 m-tiles), split hi/lo
            unsigned ah[4][4];
            unsigned al[4][4];
            #pragma unroll
            for (int mi = 0; mi < 4; mi++)
                #pragma unroll
                for (int r = 0; r < 4; r++) {
                    int row = aBase + mi * 16 + gr + (r & 1) * 8;
                    int k   = ks * 8 + ct + (r >> 1) * 4;
                    float v = As[cur][row][k];
                    unsigned h = __float_as_uint(v) & 0xFFFFE000u;
                    ah[mi][r] = h;
                    al[mi][r] = __float_as_uint(v - __uint_as_float(h));
                }
            #pragma unroll
            for (int nj = 0; nj < 4; nj++) {
                unsigned bh[2], bl[2];
                #pragma unroll
                for (int r = 0; r < 2; r++) {
                    int row = bBase + nj * 8 + gr;
                    int k   = ks * 8 + ct + r * 4;
                    float v = Bs[cur][row][k];
                    unsigned h = __float_as_uint(v) & 0xFFFFE000u;
                    bh[r] = h;
                    bl[r] = __float_as_uint(v - __uint_as_float(h));
                }
                #pragma unroll
                for (int mi = 0; mi < 4; mi++) {
                    MMA3(acc[mi][nj], ah[mi], bh);   // hi*hi
                    MMA3(acc[mi][nj], ah[mi], bl);   // hi*lo
                    MMA3(acc[mi][nj], al[mi], bh);   // lo*hi
                }
            }
        }
        if (kk + 1 < NIT) STORE_TILE(nxt);
        __syncthreads();
    }
#undef STORE_TILE

    const float w = 0.5f / fmaxf(varq[0], 1e-10f);
    #pragma unroll
    for (int nj = 0; nj < 4; nj++) {
        int col = colBase + bBase + nj * 8 + ct * 2;
        float cc0 = g_cc[col], cc1 = g_cc[col + 1];
        #pragma unroll
        for (int mi = 0; mi < 4; mi++) {
            int row = rowBase + aBase + mi * 16 + gr;
            float2 v;
            v.x = w * (2.f * acc[mi][nj][0] - cc0);
            v.y = w * (2.f * acc[mi][nj][1] - cc1);
            *(float2*)&g_logits[(size_t)row * KC + col] = v;
            v.x = w * (2.f * acc[mi][nj][2] - cc0);
            v.y = w * (2.f * acc[mi][nj][3] - cc1);
            *(float2*)&g_logits[(size_t)(row + 8) * KC + col] = v;
        }
    }
}

// ---------------- mega kernel: stats + colsum + sparse gumbel decode + diff ----
#define CCAP 256
__global__ __launch_bounds__(256) void k_mega(const float* __restrict__ Z,
                                              const float* __restrict__ CB,
                                              float* __restrict__ out) {
    const int n = blockIdx.x;
    const float* __restrict__ lrow = g_logits + (size_t)n * KC;
    const unsigned ibase = (unsigned)n * KC;
    const int t = threadIdx.x;

    float m1 = -3.0e30f, Z1 = 0.f, T1 = 0.f;
    for (int k = t * 4; k < KC; k += 1024) {
        float4 l4 = *(const float4*)(lrow + k);
        #pragma unroll
        for (int q = 0; q < 4; q++) {
            float l = (q == 0) ? l4.x : (q == 1) ? l4.y : (q == 2) ? l4.z : l4.w;
            float mn = fmaxf(m1, l);
            float d  = fmaxf(m1 - mn, -100.f);   // finite: kills -inf*0 at init
            float sc = __expf(d);
            float e  = __expf(l - mn);
            T1 = sc * (T1 + d * Z1) + e * (l - mn);
            Z1 = sc * Z1 + e;
            m1 = mn;
        }
    }
    __shared__ float sm[256], sz[256], st[256];
    __shared__ float s_fin[6];
    __shared__ int ccnt;
    __shared__ int   cidx[CCAP];
    __shared__ float cy[CCAP];
    sm[t] = m1; sz[t] = Z1; st[t] = T1;
    __syncthreads();
    for (int s = 128; s; s >>= 1) {
        if (t < s) {
            int o = t + s;
            float M = fmaxf(sm[t], sm[o]);
            float da = sm[t] - M, db = sm[o] - M;
            float ea = __expf(da), eb = __expf(db);
            st[t] = ea * (st[t] + da * sz[t]) + eb * (st[o] + db * sz[o]);
            sz[t] = ea * sz[t] + eb * sz[o];
            sm[t] = M;
        }
        __syncthreads();
    }
    if (t == 0) {
        float M = sm[0], Zz = sz[0], T = st[0];
        atomicAdd(&g_scal[0], T / Zz - logf(Zz));   // exact row sum p*logp
        s_fin[0] = M;
        s_fin[1] = 1.f / Zz;
        s_fin[2] = M + logf(Zz) - 20.723f;          // p > 1e-9 cut
        s_fin[3] = M - 28.5f;                       // candidate cut
        ccnt = 0;
    }
    __syncthreads();
    const float m1v = s_fin[0], iZ1 = s_fin[1], lpc = s_fin[2], ccut = s_fin[3];

    for (int k = t * 4; k < KC; k += 1024) {
        float4 l4 = *(const float4*)(lrow + k);
        #pragma unroll
        for (int q = 0; q < 4; q++) {
            float l = (q == 0) ? l4.x : (q == 1) ? l4.y : (q == 2) ? l4.z : l4.w;
            if (l > lpc)
                atomicAdd(&g_colsum[k + q], __expf(l - m1v) * iZ1);
            if (l > ccut) {
                int s = atomicAdd(&ccnt, 1);
                if (s < CCAP) {
                    cidx[s] = k + q;
                    cy[s]   = 2.0f * (l + gumbel_of(ibase + k + q));
                }
            }
        }
    }
    __syncthreads();
    const int cnt = min(ccnt, CCAP);

    // m2 = max over candidates
    float lm = -1e30f;
    for (int j = t; j < cnt; j += 256) lm = fmaxf(lm, cy[j]);
    sm[t] = lm;
    __syncthreads();
    for (int s = 128; s; s >>= 1) {
        if (t < s) sm[t] = fmaxf(sm[t], sm[t + s]);
        __syncthreads();
    }
    if (t == 0) s_fin[4] = sm[0];
    __syncthreads();
    const float m2v = s_fin[4];

    // Z2 over candidates
    float lz = 0.f;
    for (int j = t; j < cnt; j += 256) lz += __expf(cy[j] - m2v);
    sm[t] = lz;
    __syncthreads();
    for (int s = 128; s; s >>= 1) {
        if (t < s) sm[t] += sm[t + s];
        __syncthreads();
    }
    if (t == 0) s_fin[5] = 1.f / sm[0];
    __syncthreads();
    const float iZ2 = s_fin[5];
    for (int j = t; j < cnt; j += 256) cy[j] = __expf(cy[j] - m2v) * iZ2;
    __syncthreads();

    // decode: z_dec[n][:] = sum_j E_j * CB[cidx_j][:]; fused diff^2
    const int c0 = t * 2;
    float a0 = 0.f, a1 = 0.f;
    for (int j = 0; j < cnt; j++) {
        float e = cy[j];
        float2 cb = *(const float2*)(CB + (size_t)cidx[j] * DD + c0);
        a0 += e * cb.x;
        a1 += e * cb.y;
    }
    out[(size_t)n * DD + c0]     = a0;
    out[(size_t)n * DD + c0 + 1] = a1;
    float2 z2 = *(const float2*)(Z + (size_t)n * DD + c0);
    float d0 = z2.x - a0, d1 = z2.y - a1;
    sm[t] = d0 * d0 + d1 * d1;
    __syncthreads();
    for (int s = 128; s; s >>= 1) {
        if (t < s) sm[t] += sm[t + s];
        __syncthreads();
    }
    if (t == 0) atomicAdd(&g_scal[1], sm[0]);
}

// ---------------- finalize loss + perplexity ----------------
__global__ __launch_bounds__(256) void k_final(const float* __restrict__ varq,
                                               float* __restrict__ out, int out_size) {
    __shared__ float sh[256];
    float s = 0.f;
    for (int k = threadIdx.x; k < KC; k += 256) {
        float a = g_colsum[k] * (1.0f / (float)NR);
        s += a * logf(a + 1e-7f);
    }
    sh[threadIdx.x] = s;
    __syncthreads();
    for (int t = 128; t; t >>= 1) {
        if (threadIdx.x < t) sh[threadIdx.x] += sh[threadIdx.x + t];
        __syncthreads();
    }
    if (threadIdx.x == 0) {
        float w = 0.5f / fmaxf(varq[0], 1e-10f);
        float loss = g_scal[0] / (float)BSZ + w * g_scal[1] / (float)BSZ;
        float perp = expf(-sh[0]);
        if (out_size >= NR * DD + 2) {
            out[(size_t)NR * DD]     = loss;
            out[(size_t)NR * DD + 1] = perp;
        }
    }
}

// ---------------- launch ----------------
extern "C" void kernel_launch(void* const* d_in, const int* in_sizes, int n_in,
                              void* d_out, int out_size) {
    const float *Z = 0, *varq = 0, *CB = 0;
    for (int i = 0; i < n_in; i++) {
        if (in_sizes[i] == 1)            varq = (const float*)d_in[i];
        else if (in_sizes[i] == NR * DD) Z    = (const float*)d_in[i];
        else if (in_sizes[i] == KC * DD) CB   = (const float*)d_in[i];
    }
    float* out = (float*)d_out;

    k_zero<<<(KC + 255) / 256, 256>>>();
    k_sumsq<<<(KC * 32 + 255) / 256, 256>>>(CB);
    k_gemm_logits<<<dim3(KC / 128, NR / 128), 256>>>(Z, CB, varq);
    k_mega<<<NR, 256>>>(Z, CB, out);
    k_final<<<1, 256>>>(varq, out, out_size);
}

// round 15
// speedup vs baseline: 1.6932x; 1.0378x over previous
#include <cuda_runtime.h>
#include <math.h>
#include <stdint.h>

// Problem dims (fixed by the dataset)
#define NR 4096           // bs*seq
#define KC 8192           // codebook size
#define DD 512            // feature dim
#define BSZ 8
#define TOT (NR * KC)

// ---------------- scratch (static __device__, allocation-free) ----------------
__device__ float g_logits[(size_t)NR * KC];   // 134 MB
__device__ float g_cc[KC];
__device__ float g_colsum[KC];
__device__ float g_scal[2];  // [0] = sum(p*logp), [1] = sum(diff^2)

// ---------------- zero accumulators (graph replays!) ----------------
__global__ void k_zero() {
    int i = blockIdx.x * blockDim.x + threadIdx.x;
    if (i < KC) g_colsum[i] = 0.f;
    if (i < 2)  g_scal[i]   = 0.f;
}

// ---------------- codebook squared norms ----------------
__global__ void k_sumsq(const float* __restrict__ CB) {
    int warp = (blockIdx.x * blockDim.x + threadIdx.x) >> 5;
    int lane = threadIdx.x & 31;
    if (warp >= KC) return;
    const float* p = CB + (size_t)warp * DD;
    float s = 0.f;
    #pragma unroll 4
    for (int i = lane; i < DD; i += 32) { float v = p[i]; s += v * v; }
    #pragma unroll
    for (int o = 16; o; o >>= 1) s += __shfl_xor_sync(0xffffffffu, s, o);
    if (lane == 0) g_cc[warp] = s;
}

// ---------------- Threefry-2x32 gumbel (partitionable), pure fn of index ------
__device__ __forceinline__ float gumbel_of(unsigned i) {
    unsigned x0 = 0u, x1 = i;
    const unsigned k0 = 0u, k1 = 42u, k2 = 0x1BD11BDAu ^ k0 ^ k1;
    x0 += k0; x1 += k1;
#define TFR(r) { x0 += x1; x1 = __funnelshift_l(x1, x1, r); x1 ^= x0; }
    TFR(13) TFR(15) TFR(26) TFR(6)   x0 += k1; x1 += k2 + 1u;
    TFR(17) TFR(29) TFR(16) TFR(24)  x0 += k2; x1 += k0 + 2u;
    TFR(13) TFR(15) TFR(26) TFR(6)   x0 += k0; x1 += k1 + 3u;
    TFR(17) TFR(29) TFR(16) TFR(24)  x0 += k1; x1 += k2 + 4u;
    TFR(13) TFR(15) TFR(26) TFR(6)   x0 += k2; x1 += k0 + 5u;
#undef TFR
    unsigned bits = x0 ^ x1;
    float u = __uint_as_float(0x3f800000u | (bits >> 9)) - 1.0f;
    float x = u - 1.0f;                       // exact (Sterbenz) for u in [0.5,1]
    float pl = 1.f + x * (-0.5f + x * (0.33333334f + x * (-0.25f +
               x * (0.2f + x * (-0.16666667f + x * 0.14285715f)))));
    float ts = -x * pl;                       // accurate -ln(u), u near 1
    float tm = -__logf(u + 1e-10f);
    float t = (u > 0.9f) ? ts : tm;
    return -__logf(t + 1e-10f);
}

// ---------------- GEMM1 via mma.sync tf32 (3-way split) ----------------------
// logits[n,k] = w*(2*Z.C^T - cc). 128x128x16 CTA tile, 256 threads.
// Warps z-order 2x4; warp tile 64x32 = 4x4 m16n8k8 fragments.
// smem untransposed [row][k] with pitch 20: fragment LDS conflict-free.
#define BK1 16
#define KP 20
#define MMA3(d, A, B) asm volatile( \
    "mma.sync.aligned.m16n8k8.row.col.f32.tf32.tf32.f32 " \
    "{%0,%1,%2,%3}, {%4,%5,%6,%7}, {%8,%9}, {%0,%1,%2,%3};" \
    : "+f"((d)[0]), "+f"((d)[1]), "+f"((d)[2]), "+f"((d)[3]) \
    : "r"((A)[0]), "r"((A)[1]), "r"((A)[2]), "r"((A)[3]), \
      "r"((B)[0]), "r"((B)[1]))

__global__ __launch_bounds__(256, 2) void k_gemm_logits(
    const float* __restrict__ Z, const float* __restrict__ CB,
    const float* __restrict__ varq) {
    __shared__ __align__(16) float As[2][128][KP];
    __shared__ __align__(16) float Bs[2][128][KP];
    const int tid = threadIdx.x;
    const int lane = tid & 31, warp = tid >> 5;
    const int gr = lane >> 2, ct = lane & 3;
    const int warpRow = warp & 1, warpCol = warp >> 1;
    const int aBase = warpRow * 64;        // warp row offset (64 rows)
    const int bBase = warpCol * 32;        // warp col offset (32 cols)
    const int rowBase = blockIdx.y * 128, colBase = blockIdx.x * 128;
    const int lr = tid >> 2;     // 0..63 loader row
    const int lc = tid & 3;      // 0..3  loader k-slot

    const float* Ap = Z  + (size_t)(rowBase + lr) * DD + lc * 4;
    const float* Bp = CB + (size_t)(colBase + lr) * DD + lc * 4;

    float4 va0 = *(const float4*)(Ap);
    float4 va1 = *(const float4*)(Ap + 64 * DD);
    float4 vb0 = *(const float4*)(Bp);
    float4 vb1 = *(const float4*)(Bp + 64 * DD);

#define STORE_TILE(buf) do {                             \
    *(float4*)&As[buf][lr][lc * 4]      = va0;           \
    *(float4*)&As[buf][lr + 64][lc * 4] = va1;           \
    *(float4*)&Bs[buf][lr][lc * 4]      = vb0;           \
    *(float4*)&Bs[buf][lr + 64][lc * 4] = vb1;           \
} while (0)

    STORE_TILE(0);
    __syncthreads();

    float acc[4][4][4];
    #pragma unroll
    for (int mi = 0; mi < 4; mi++)
        #pragma unroll
        for (int nj = 0; nj < 4; nj++)
            #pragma unroll
            for (int r = 0; r < 4; r++) acc[mi][nj][r] = 0.f;

    const int NIT = DD / BK1;   // 32
    for (int kk = 0; kk < NIT; kk++) {
        const int cur = kk & 1, nxt = cur ^ 1;
        if (kk + 1 < NIT) {
            const float* Ap2 = Ap + (kk + 1) * BK1;
            const float* Bp2 = Bp + (kk + 1) * BK1;
            va0 = *(const float4*)(Ap2);
            va1 = *(const float4*)(Ap2 + 64 * DD);
            vb0 = *(const float4*)(Bp2);
            vb1 = *(const float4*)(Bp2 + 64 * DD);
        }
        #pragma unroll
        for (int ks = 0; ks < 2; ks++) {
            unsigned ah[4][4];
            unsigned al[4][4];
            #pragma unroll
            for (int mi = 0; mi < 4; mi++)
                #pragma unroll
                for (int r = 0; r < 4; r++) {
                    int row = aBase + mi * 16 + gr + (r & 1) * 8;
                    int k   = ks * 8 + ct + (r >> 1) * 4;
                    float v = As[cur][row][k];
                    unsigned h = __float_as_uint(v) & 0xFFFFE000u;
                    ah[mi][r] = h;
                    al[mi][r] = __float_as_uint(v - __uint_as_float(h));
                }
            #pragma unroll
            for (int nj = 0; nj < 4; nj++) {
                unsigned bh[2], bl[2];
                #pragma unroll
                for (int r = 0; r < 2; r++) {
                    int row = bBase + nj * 8 + gr;
                    int k   = ks * 8 + ct + r * 4;
                    float v = Bs[cur][row][k];
                    unsigned h = __float_as_uint(v) & 0xFFFFE000u;
                    bh[r] = h;
                    bl[r] = __float_as_uint(v - __uint_as_float(h));
                }
                #pragma unroll
                for (int mi = 0; mi < 4; mi++) {
                    MMA3(acc[mi][nj], ah[mi], bh);   // hi*hi
                    MMA3(acc[mi][nj], ah[mi], bl);   // hi*lo
                    MMA3(acc[mi][nj], al[mi], bh);   // lo*hi
                }
            }
        }
        if (kk + 1 < NIT) STORE_TILE(nxt);
        __syncthreads();
    }
#undef STORE_TILE

    const float w = 0.5f / fmaxf(varq[0], 1e-10f);
    #pragma unroll
    for (int nj = 0; nj < 4; nj++) {
        int col = colBase + bBase + nj * 8 + ct * 2;
        float cc0 = g_cc[col], cc1 = g_cc[col + 1];
        #pragma unroll
        for (int mi = 0; mi < 4; mi++) {
            int row = rowBase + aBase + mi * 16 + gr;
            float2 v;
            v.x = w * (2.f * acc[mi][nj][0] - cc0);
            v.y = w * (2.f * acc[mi][nj][1] - cc1);
            *(float2*)&g_logits[(size_t)row * KC + col] = v;
            v.x = w * (2.f * acc[mi][nj][2] - cc0);
            v.y = w * (2.f * acc[mi][nj][3] - cc1);
            *(float2*)&g_logits[(size_t)(row + 8) * KC + col] = v;
        }
    }
}

// ---------------- mega kernel: max-pass + fused stats/candidates + decode -----
// Pass A: row max m1 (pure fmax).
// Pass B: fixed-m1 stats (1 exp + 3 fma per elem) + candidates (d > -28.5).
//   Colsum-eligible (p>1e-9 <=> d > logZ1-20.72, logZ1>=0) is a SUBSET of
//   candidates, so colsum atomics run over the cached list only.
#define CCAP 256
__global__ __launch_bounds__(256) void k_mega(const float* __restrict__ Z,
                                              const float* __restrict__ CB,
                                              float* __restrict__ out) {
    const int n = blockIdx.x;
    const float* __restrict__ lrow = g_logits + (size_t)n * KC;
    const unsigned ibase = (unsigned)n * KC;
    const int t = threadIdx.x;

    __shared__ float sm[256], sz[256];
    __shared__ float s_fin[4];
    __shared__ int ccnt;
    __shared__ int   cidx[CCAP];
    __shared__ float cv[CCAP];   // logit l, later E

    // ---- Pass A: row max (two independent accumulators for ILP) ----
    float ma = -3.0e30f, mb = -3.0e30f;
    for (int k = t * 4; k < KC; k += 1024) {
        float4 l4 = *(const float4*)(lrow + k);
        ma = fmaxf(ma, fmaxf(l4.x, l4.y));
        mb = fmaxf(mb, fmaxf(l4.z, l4.w));
    }
    sm[t] = fmaxf(ma, mb);
    __syncthreads();
    for (int s = 128; s; s >>= 1) {
        if (t < s) sm[t] = fmaxf(sm[t], sm[t + s]);
        __syncthreads();
    }
    if (t == 0) { s_fin[0] = sm[0]; ccnt = 0; }
    __syncthreads();
    const float m1v = s_fin[0];

    // ---- Pass B: Z1, T1 with fixed m1; candidate capture ----
    float Z1 = 0.f, T1 = 0.f;
    for (int k = t * 4; k < KC; k += 1024) {
        float4 l4 = *(const float4*)(lrow + k);
        #pragma unroll
        for (int q = 0; q < 4; q++) {
            float l = (q == 0) ? l4.x : (q == 1) ? l4.y : (q == 2) ? l4.z : l4.w;
            float d = l - m1v;
            float e = __expf(d);
            Z1 += e; T1 += e * d;
            if (d > -28.5f) {
                int s = atomicAdd(&ccnt, 1);
                if (s < CCAP) { cidx[s] = k + q; cv[s] = l; }
            }
        }
    }
    sm[t] = T1; sz[t] = Z1;
    __syncthreads();
    for (int s = 128; s; s >>= 1) {
        if (t < s) { sm[t] += sm[t + s]; sz[t] += sz[t + s]; }
        __syncthreads();
    }
    if (t == 0) {
        float Zz = sz[0], T = sm[0];
        atomicAdd(&g_scal[0], T / Zz - logf(Zz));   // exact row sum p*logp
        s_fin[1] = 1.f / Zz;                        // iZ1
        s_fin[2] = logf(Zz) - 20.723f;              // colsum cut on d
    }
    __syncthreads();
    const float iZ1 = s_fin[1], dpc = s_fin[2];
    const int cnt = min(ccnt, CCAP);

    // ---- colsum over candidates ----
    for (int j = t; j < cnt; j += 256) {
        float d = cv[j] - m1v;
        if (d > dpc) atomicAdd(&g_colsum[cidx[j]], __expf(d) * iZ1);
    }

    // ---- gumbel y for candidates ----
    __syncthreads();
    for (int j = t; j < cnt; j += 256)
        cv[j] = 2.0f * (cv[j] + gumbel_of(ibase + cidx[j]));
    __syncthreads();

    // m2 = max over candidates
    float lm = -1e30f;
    for (int j = t; j < cnt; j += 256) lm = fmaxf(lm, cv[j]);
    sm[t] = lm;
    __syncthreads();
    for (int s = 128; s; s >>= 1) {
        if (t < s) sm[t] = fmaxf(sm[t], sm[t + s]);
        __syncthreads();
    }
    if (t == 0) s_fin[0] = sm[0];
    __syncthreads();
    const float m2v = s_fin[0];

    // Z2 over candidates
    float lz = 0.f;
    for (int j = t; j < cnt; j += 256) lz += __expf(cv[j] - m2v);
    sm[t] = lz;
    __syncthreads();
    for (int s = 128; s; s >>= 1) {
        if (t < s) sm[t] += sm[t + s];
        __syncthreads();
    }
    if (t == 0) s_fin[3] = 1.f / sm[0];
    __syncthreads();
    const float iZ2 = s_fin[3];
    for (int j = t; j < cnt; j += 256) cv[j] = __expf(cv[j] - m2v) * iZ2;
    __syncthreads();

    // decode: z_dec[n][:] = sum_j E_j * CB[cidx_j][:]; fused diff^2
    const int c0 = t * 2;
    float a0 = 0.f, a1 = 0.f;
    for (int j = 0; j < cnt; j++) {
        float e = cv[j];
        float2 cb = *(const float2*)(CB + (size_t)cidx[j] * DD + c0);
        a0 += e * cb.x;
        a1 += e * cb.y;
    }
    out[(size_t)n * DD + c0]     = a0;
    out[(size_t)n * DD + c0 + 1] = a1;
    float2 z2 = *(const float2*)(Z + (size_t)n * DD + c0);
    float d0 = z2.x - a0, d1 = z2.y - a1;
    sm[t] = d0 * d0 + d1 * d1;
    __syncthreads();
    for (int s = 128; s; s >>= 1) {
        if (t < s) sm[t] += sm[t + s];
        __syncthreads();
    }
    if (t == 0) atomicAdd(&g_scal[1], sm[0]);
}

// ---------------- finalize loss + perplexity ----------------
__global__ __launch_bounds__(256) void k_final(const float* __restrict__ varq,
                                               float* __restrict__ out, int out_size) {
    __shared__ float sh[256];
    float s = 0.f;
    for (int k = threadIdx.x; k < KC; k += 256) {
        float a = g_colsum[k] * (1.0f / (float)NR);
        s += a * logf(a + 1e-7f);
    }
    sh[threadIdx.x] = s;
    __syncthreads();
    for (int t = 128; t; t >>= 1) {
        if (threadIdx.x < t) sh[threadIdx.x] += sh[threadIdx.x + t];
        __syncthreads();
    }
    if (threadIdx.x == 0) {
        float w = 0.5f / fmaxf(varq[0], 1e-10f);
        float loss = g_scal[0] / (float)BSZ + w * g_scal[1] / (float)BSZ;
        float perp = expf(-sh[0]);
        if (out_size >= NR * DD + 2) {
            out[(size_t)NR * DD]     = loss;
            out[(size_t)NR * DD + 1] = perp;
        }
    }
}

// ---------------- launch ----------------
extern "C" void kernel_launch(void* const* d_in, const int* in_sizes, int n_in,
                              void* d_out, int out_size) {
    const float *Z = 0, *varq = 0, *CB = 0;
    for (int i = 0; i < n_in; i++) {
        if (in_sizes[i] == 1)            varq = (const float*)d_in[i];
        else if (in_sizes[i] == NR * DD) Z    = (const float*)d_in[i];
        else if (in_sizes[i] == KC * DD) CB   = (const float*)d_in[i];
    }
    float* out = (float*)d_out;

    k_zero<<<(KC + 255) / 256, 256>>>();
    k_sumsq<<<(KC * 32 + 255) / 256, 256>>>(CB);
    k_gemm_logits<<<dim3(KC / 128, NR / 128), 256>>>(Z, CB, varq);
    k_mega<<<NR, 256>>>(Z, CB, out);
    k_final<<<1, 256>>>(varq, out, out_size);
}

// round 16
// speedup vs baseline: 1.7184x; 1.0149x over previous
#include <cuda_runtime.h>
#include <math.h>
#include <stdint.h>

// Problem dims (fixed by the dataset)
#define NR 4096           // bs*seq
#define KC 8192           // codebook size
#define DD 512            // feature dim
#define BSZ 8
#define TOT (NR * KC)

// ---------------- scratch (static __device__, allocation-free) ----------------
__device__ float g_logits[(size_t)NR * KC];   // 134 MB
__device__ float g_cc[KC];
__device__ float g_colsum[KC];
__device__ unsigned g_m1i[NR];                // ordered-int row max
__device__ float g_scal[2];  // [0] = sum(p*logp), [1] = sum(diff^2)

// ordered-int float encoding (monotone): enc(a)<enc(b) <=> a<b
__device__ __forceinline__ unsigned enc_f(float f) {
    unsigned b = __float_as_uint(f);
    return (b & 0x80000000u) ? ~b : (b | 0x80000000u);
}
__device__ __forceinline__ float dec_f(unsigned u) {
    unsigned b = (u & 0x80000000u) ? (u ^ 0x80000000u) : ~u;
    return __uint_as_float(b);
}

// ---------------- codebook norms + accumulator init (graph replays!) ----------
__global__ void k_sumsq(const float* __restrict__ CB) {
    int gt = blockIdx.x * blockDim.x + threadIdx.x;
    if (gt < KC) g_colsum[gt] = 0.f;
    if (gt < NR) g_m1i[gt] = 0u;         // decodes below any real logit
    if (gt < 2)  g_scal[gt] = 0.f;
    int warp = gt >> 5;
    int lane = threadIdx.x & 31;
    if (warp >= KC) return;
    const float* p = CB + (size_t)warp * DD;
    float s = 0.f;
    #pragma unroll 4
    for (int i = lane; i < DD; i += 32) { float v = p[i]; s += v * v; }
    #pragma unroll
    for (int o = 16; o; o >>= 1) s += __shfl_xor_sync(0xffffffffu, s, o);
    if (lane == 0) g_cc[warp] = s;
}

// ---------------- Threefry-2x32 gumbel (partitionable), pure fn of index ------
__device__ __forceinline__ float gumbel_of(unsigned i) {
    unsigned x0 = 0u, x1 = i;
    const unsigned k0 = 0u, k1 = 42u, k2 = 0x1BD11BDAu ^ k0 ^ k1;
    x0 += k0; x1 += k1;
#define TFR(r) { x0 += x1; x1 = __funnelshift_l(x1, x1, r); x1 ^= x0; }
    TFR(13) TFR(15) TFR(26) TFR(6)   x0 += k1; x1 += k2 + 1u;
    TFR(17) TFR(29) TFR(16) TFR(24)  x0 += k2; x1 += k0 + 2u;
    TFR(13) TFR(15) TFR(26) TFR(6)   x0 += k0; x1 += k1 + 3u;
    TFR(17) TFR(29) TFR(16) TFR(24)  x0 += k1; x1 += k2 + 4u;
    TFR(13) TFR(15) TFR(26) TFR(6)   x0 += k2; x1 += k0 + 5u;
#undef TFR
    unsigned bits = x0 ^ x1;
    float u = __uint_as_float(0x3f800000u | (bits >> 9)) - 1.0f;
    float x = u - 1.0f;                       // exact (Sterbenz) for u in [0.5,1]
    float pl = 1.f + x * (-0.5f + x * (0.33333334f + x * (-0.25f +
               x * (0.2f + x * (-0.16666667f + x * 0.14285715f)))));
    float ts = -x * pl;                       // accurate -ln(u), u near 1
    float tm = -__logf(u + 1e-10f);
    float t = (u > 0.9f) ? ts : tm;
    return -__logf(t + 1e-10f);
}

// ---------------- GEMM1 via mma.sync tf32 (3-way split) ----------------------
// logits[n,k] = w*(2*Z.C^T - cc). 128x128x16 CTA tile, 256 threads.
// Warps z-order 2x4; warp tile 64x32 = 4x4 m16n8k8 fragments.
// smem untransposed [row][k] with pitch 20: fragment LDS conflict-free.
// Epilogue additionally reduces row max -> atomicMax(g_m1i) (k_mega skips pass A).
#define BK1 16
#define KP 20
#define MMA3(d, A, B) asm volatile( \
    "mma.sync.aligned.m16n8k8.row.col.f32.tf32.tf32.f32 " \
    "{%0,%1,%2,%3}, {%4,%5,%6,%7}, {%8,%9}, {%0,%1,%2,%3};" \
    : "+f"((d)[0]), "+f"((d)[1]), "+f"((d)[2]), "+f"((d)[3]) \
    : "r"((A)[0]), "r"((A)[1]), "r"((A)[2]), "r"((A)[3]), \
      "r"((B)[0]), "r"((B)[1]))

__global__ __launch_bounds__(256, 2) void k_gemm_logits(
    const float* __restrict__ Z, const float* __restrict__ CB,
    const float* __restrict__ varq) {
    __shared__ __align__(16) float As[2][128][KP];
    __shared__ __align__(16) float Bs[2][128][KP];
    const int tid = threadIdx.x;
    const int lane = tid & 31, warp = tid >> 5;
    const int gr = lane >> 2, ct = lane & 3;
    const int warpRow = warp & 1, warpCol = warp >> 1;
    const int aBase = warpRow * 64;        // warp row offset (64 rows)
    const int bBase = warpCol * 32;        // warp col offset (32 cols)
    const int rowBase = blockIdx.y * 128, colBase = blockIdx.x * 128;
    const int lr = tid >> 2;     // 0..63 loader row
    const int lc = tid & 3;      // 0..3  loader k-slot

    const float* Ap = Z  + (size_t)(rowBase + lr) * DD + lc * 4;
    const float* Bp = CB + (size_t)(colBase + lr) * DD + lc * 4;

    float4 va0 = *(const float4*)(Ap);
    float4 va1 = *(const float4*)(Ap + 64 * DD);
    float4 vb0 = *(const float4*)(Bp);
    float4 vb1 = *(const float4*)(Bp + 64 * DD);

#define STORE_TILE(buf) do {                             \
    *(float4*)&As[buf][lr][lc * 4]      = va0;           \
    *(float4*)&As[buf][lr + 64][lc * 4] = va1;           \
    *(float4*)&Bs[buf][lr][lc * 4]      = vb0;           \
    *(float4*)&Bs[buf][lr + 64][lc * 4] = vb1;           \
} while (0)

    STORE_TILE(0);
    __syncthreads();

    float acc[4][4][4];
    #pragma unroll
    for (int mi = 0; mi < 4; mi++)
        #pragma unroll
        for (int nj = 0; nj < 4; nj++)
            #pragma unroll
            for (int r = 0; r < 4; r++) acc[mi][nj][r] = 0.f;

    const int NIT = DD / BK1;   // 32
    for (int kk = 0; kk < NIT; kk++) {
        const int cur = kk & 1, nxt = cur ^ 1;
        if (kk + 1 < NIT) {
            const float* Ap2 = Ap + (kk + 1) * BK1;
            const float* Bp2 = Bp + (kk + 1) * BK1;
            va0 = *(const float4*)(Ap2);
            va1 = *(const float4*)(Ap2 + 64 * DD);
            vb0 = *(const float4*)(Bp2);
            vb1 = *(const float4*)(Bp2 + 64 * DD);
        }
        #pragma unroll
        for (int ks = 0; ks < 2; ks++) {
            unsigned ah[4][4];
            unsigned al[4][4];
            #pragma unroll
            for (int mi = 0; mi < 4; mi++)
                #pragma unroll
                for (int r = 0; r < 4; r++) {
                    int row = aBase + mi * 16 + gr + (r & 1) * 8;
                    int k   = ks * 8 + ct + (r >> 1) * 4;
                    float v = As[cur][row][k];
                    unsigned h = __float_as_uint(v) & 0xFFFFE000u;
                    ah[mi][r] = h;
                    al[mi][r] = __float_as_uint(v - __uint_as_float(h));
                }
            #pragma unroll
            for (int nj = 0; nj < 4; nj++) {
                unsigned bh[2], bl[2];
                #pragma unroll
                for (int r = 0; r < 2; r++) {
                    int row = bBase + nj * 8 + gr;
                    int k   = ks * 8 + ct + r * 4;
                    float v = Bs[cur][row][k];
                    unsigned h = __float_as_uint(v) & 0xFFFFE000u;
                    bh[r] = h;
                    bl[r] = __float_as_uint(v - __uint_as_float(h));
                }
                #pragma unroll
                for (int mi = 0; mi < 4; mi++) {
                    MMA3(acc[mi][nj], ah[mi], bh);   // hi*hi
                    MMA3(acc[mi][nj], ah[mi], bl);   // hi*lo
                    MMA3(acc[mi][nj], al[mi], bh);   // lo*hi
                }
            }
        }
        if (kk + 1 < NIT) STORE_TILE(nxt);
        __syncthreads();
    }
#undef STORE_TILE

    const float w = 0.5f / fmaxf(varq[0], 1e-10f);
    // logits in registers: l = w*(2*acc - cc); write + row-max capture
    float rmax[4][2];   // [mi][half]
    #pragma unroll
    for (int mi = 0; mi < 4; mi++) { rmax[mi][0] = -3e30f; rmax[mi][1] = -3e30f; }
    #pragma unroll
    for (int nj = 0; nj < 4; nj++) {
        int col = colBase + bBase + nj * 8 + ct * 2;
        float cc0 = g_cc[col], cc1 = g_cc[col + 1];
        #pragma unroll
        for (int mi = 0; mi < 4; mi++) {
            int row = rowBase + aBase + mi * 16 + gr;
            float2 v;
            v.x = w * (2.f * acc[mi][nj][0] - cc0);
            v.y = w * (2.f * acc[mi][nj][1] - cc1);
            *(float2*)&g_logits[(size_t)row * KC + col] = v;
            rmax[mi][0] = fmaxf(rmax[mi][0], fmaxf(v.x, v.y));
            v.x = w * (2.f * acc[mi][nj][2] - cc0);
            v.y = w * (2.f * acc[mi][nj][3] - cc1);
            *(float2*)&g_logits[(size_t)(row + 8) * KC + col] = v;
            rmax[mi][1] = fmaxf(rmax[mi][1], fmaxf(v.x, v.y));
        }
    }
    // reduce across the 4 ct-lanes sharing each row, then atomicMax per row
    #pragma unroll
    for (int mi = 0; mi < 4; mi++)
        #pragma unroll
        for (int h = 0; h < 2; h++) {
            float m = rmax[mi][h];
            m = fmaxf(m, __shfl_xor_sync(0xffffffffu, m, 1));
            m = fmaxf(m, __shfl_xor_sync(0xffffffffu, m, 2));
            if (ct == 0) {
                int row = rowBase + aBase + mi * 16 + gr + h * 8;
                atomicMax(&g_m1i[row], enc_f(m));
            }
        }
}

// ---------------- mega kernel: fused stats/candidates + decode -----------------
// m1 precomputed by GEMM1 epilogue (g_m1i). Single logits sweep:
//   Z1/T1 (1 exp + 3 fma per elem) + candidates (d > -28.5).
// Colsum-eligible (p>1e-9) is a subset of candidates -> atomics over list only.
#define CCAP 256
__global__ __launch_bounds__(256) void k_mega(const float* __restrict__ Z,
                                              const float* __restrict__ CB,
                                              float* __restrict__ out) {
    const int n = blockIdx.x;
    const float* __restrict__ lrow = g_logits + (size_t)n * KC;
    const unsigned ibase = (unsigned)n * KC;
    const int t = threadIdx.x;

    __shared__ float sm[256], sz[256];
    __shared__ float s_fin[4];
    __shared__ int ccnt;
    __shared__ int   cidx[CCAP];
    __shared__ float cv[CCAP];   // logit l, later E

    if (t == 0) ccnt = 0;
    __syncthreads();
    const float m1v = dec_f(g_m1i[n]);

    // ---- single pass: Z1, T1 with fixed m1; candidate capture ----
    float Z1 = 0.f, T1 = 0.f;
    for (int k = t * 4; k < KC; k += 1024) {
        float4 l4 = *(const float4*)(lrow + k);
        #pragma unroll
        for (int q = 0; q < 4; q++) {
            float l = (q == 0) ? l4.x : (q == 1) ? l4.y : (q == 2) ? l4.z : l4.w;
            float d = l - m1v;
            float e = __expf(d);
            Z1 += e; T1 += e * d;
            if (d > -28.5f) {
                int s = atomicAdd(&ccnt, 1);
                if (s < CCAP) { cidx[s] = k + q; cv[s] = l; }
            }
        }
    }
    sm[t] = T1; sz[t] = Z1;
    __syncthreads();
    for (int s = 128; s; s >>= 1) {
        if (t < s) { sm[t] += sm[t + s]; sz[t] += sz[t + s]; }
        __syncthreads();
    }
    if (t == 0) {
        float Zz = sz[0], T = sm[0];
        atomicAdd(&g_scal[0], T / Zz - logf(Zz));   // exact row sum p*logp
        s_fin[1] = 1.f / Zz;                        // iZ1
        s_fin[2] = logf(Zz) - 20.723f;              // colsum cut on d
    }
    __syncthreads();
    const float iZ1 = s_fin[1], dpc = s_fin[2];
    const int cnt = min(ccnt, CCAP);

    // ---- colsum over candidates ----
    for (int j = t; j < cnt; j += 256) {
        float d = cv[j] - m1v;
        if (d > dpc) atomicAdd(&g_colsum[cidx[j]], __expf(d) * iZ1);
    }

    // ---- gumbel y for candidates ----
    __syncthreads();
    for (int j = t; j < cnt; j += 256)
        cv[j] = 2.0f * (cv[j] + gumbel_of(ibase + cidx[j]));
    __syncthreads();

    // m2 = max over candidates
    float lm = -1e30f;
    for (int j = t; j < cnt; j += 256) lm = fmaxf(lm, cv[j]);
    sm[t] = lm;
    __syncthreads();
    for (int s = 128; s; s >>= 1) {
        if (t < s) sm[t] = fmaxf(sm[t], sm[t + s]);
        __syncthreads();
    }
    if (t == 0) s_fin[0] = sm[0];
    __syncthreads();
    const float m2v = s_fin[0];

    // Z2 over candidates
    float lz = 0.f;
    for (int j = t; j < cnt; j += 256) lz += __expf(cv[j] - m2v);
    sm[t] = lz;
    __syncthreads();
    for (int s = 128; s; s >>= 1) {
        if (t < s) sm[t] += sm[t + s];
        __syncthreads();
    }
    if (t == 0) s_fin[3] = 1.f / sm[0];
    __syncthreads();
    const float iZ2 = s_fin[3];
    for (int j = t; j < cnt; j += 256) cv[j] = __expf(cv[j] - m2v) * iZ2;
    __syncthreads();

    // decode: z_dec[n][:] = sum_j E_j * CB[cidx_j][:]; fused diff^2
    const int c0 = t * 2;
    float a0 = 0.f, a1 = 0.f;
    for (int j = 0; j < cnt; j++) {
        float e = cv[j];
        float2 cb = *(const float2*)(CB + (size_t)cidx[j] * DD + c0);
        a0 += e * cb.x;
        a1 += e * cb.y;
    }
    out[(size_t)n * DD + c0]     = a0;
    out[(size_t)n * DD + c0 + 1] = a1;
    float2 z2 = *(const float2*)(Z + (size_t)n * DD + c0);
    float d0 = z2.x - a0, d1 = z2.y - a1;
    sm[t] = d0 * d0 + d1 * d1;
    __syncthreads();
    for (int s = 128; s; s >>= 1) {
        if (t < s) sm[t] += sm[t + s];
        __syncthreads();
    }
    if (t == 0) atomicAdd(&g_scal[1], sm[0]);
}

// ---------------- finalize loss + perplexity ----------------
__global__ __launch_bounds__(256) void k_final(const float* __restrict__ varq,
                                               float* __restrict__ out, int out_size) {
    __shared__ float sh[256];
    float s = 0.f;
    for (int k = threadIdx.x; k < KC; k += 256) {
        float a = g_colsum[k] * (1.0f / (float)NR);
        s += a * logf(a + 1e-7f);
    }
    sh[threadIdx.x] = s;
    __syncthreads();
    for (int t = 128; t; t >>= 1) {
        if (threadIdx.x < t) sh[threadIdx.x] += sh[threadIdx.x + t];
        __syncthreads();
    }
    if (threadIdx.x == 0) {
        float w = 0.5f / fmaxf(varq[0], 1e-10f);
        float loss = g_scal[0] / (float)BSZ + w * g_scal[1] / (float)BSZ;
        float perp = expf(-sh[0]);
        if (out_size >= NR * DD + 2) {
            out[(size_t)NR * DD]     = loss;
            out[(size_t)NR * DD + 1] = perp;
        }
    }
}

// ---------------- launch ----------------
extern "C" void kernel_launch(void* const* d_in, const int* in_sizes, int n_in,
                              void* d_out, int out_size) {
    const float *Z = 0, *varq = 0, *CB = 0;
    for (int i = 0; i < n_in; i++) {
        if (in_sizes[i] == 1)            varq = (const float*)d_in[i];
        else if (in_sizes[i] == NR * DD) Z    = (const float*)d_in[i];
        else if (in_sizes[i] == KC * DD) CB   = (const float*)d_in[i];
    }
    float* out = (float*)d_out;

    k_sumsq<<<(KC * 32 + 255) / 256, 256>>>(CB);   // also inits colsum/m1i/scal
    k_gemm_logits<<<dim3(KC / 128, NR / 128), 256>>>(Z, CB, varq);
    k_mega<<<NR, 256>>>(Z, CB, out);
    k_final<<<1, 256>>>(varq, out, out_size);
}